// round 11
// baseline (speedup 1.0000x reference)
#include <cuda_runtime.h>
#include <cuda_bf16.h>
#include <cstdint>

// ---------------------------------------------------------------------------
// PCA-whitening norm. x: [64,64,128,128] fp32.  HMMA, 64-px tiles, cp.async.
//   1. gram_mma  : staged fp32 -> bf16 h/l -> P1=xh@xh^T, P2=xl@xh^T
//   2. reduce_kernel : gram = sum(P1 + P2 + P2^T), channel sums
//   3. eigen_kernel  : -> g_W, g_off
//   4. apply_mma : out = W@x + off, K=192 bf16-split HMMA, staged conversion
// ---------------------------------------------------------------------------

#define CCH    64
#define HWSZ   16384
#define NT2    16384         // 64-px tiles
#define GBLK   444
#define KEIG   32
#define EPSV   1e-5f

__device__ float g_p1[GBLK * 4096];
__device__ float g_p2[GBLK * 4096];
__device__ float g_ps[GBLK * 64];
__device__ float g_gram[4096];
__device__ float g_S[64];
__device__ float g_W[4096];
__device__ float g_off[64];

// ---------------- helpers ----------------
__device__ __forceinline__ uint32_t smem_u32(const void* p) {
    return (uint32_t)__cvta_generic_to_shared(p);
}
__device__ __forceinline__ uint32_t cvt_bf2(float a, float b) {
    uint32_t d;
    asm("cvt.rn.bf16x2.f32 %0, %1, %2;" : "=r"(d) : "f"(b), "f"(a));
    return d;
}
__device__ __forceinline__ void ldsm4(uint32_t* r, uint32_t addr) {
    asm volatile("ldmatrix.sync.aligned.m8n8.x4.shared.b16 {%0,%1,%2,%3}, [%4];"
                 : "=r"(r[0]), "=r"(r[1]), "=r"(r[2]), "=r"(r[3]) : "r"(addr));
}
__device__ __forceinline__ void ldsm4t(uint32_t* r, uint32_t addr) {
    asm volatile("ldmatrix.sync.aligned.m8n8.x4.trans.shared.b16 {%0,%1,%2,%3}, [%4];"
                 : "=r"(r[0]), "=r"(r[1]), "=r"(r[2]), "=r"(r[3]) : "r"(addr));
}
__device__ __forceinline__ void mma16816(float* d, const uint32_t* a,
                                         uint32_t b0, uint32_t b1) {
    asm volatile("mma.sync.aligned.m16n8k16.row.col.f32.bf16.bf16.f32 "
                 "{%0,%1,%2,%3}, {%4,%5,%6,%7}, {%8,%9}, {%0,%1,%2,%3};"
                 : "+f"(d[0]), "+f"(d[1]), "+f"(d[2]), "+f"(d[3])
                 : "r"(a[0]), "r"(a[1]), "r"(a[2]), "r"(a[3]), "r"(b0), "r"(b1));
}
__device__ __forceinline__ void sts64(uint32_t addr, uint32_t r0, uint32_t r1) {
    asm volatile("st.shared.v2.b32 [%0], {%1, %2};" :: "r"(addr), "r"(r0), "r"(r1));
}
__device__ __forceinline__ void cpa16(void* s, const void* g) {
    uint32_t sa = (uint32_t)__cvta_generic_to_shared(s);
    asm volatile("cp.async.cg.shared.global [%0], [%1], 16;" :: "r"(sa), "l"(g));
}
#define CP_COMMIT asm volatile("cp.async.commit_group;")
#define CP_WAIT1  asm volatile("cp.async.wait_group 1;")

// ---------------------------------------------------------------------------
// Pass 1: gram.  64ch x 64px tiles, cp.async staged, 3 CTAs/SM.
// F: fp32 [ch][px] 256B rows (16KB x2). XH/XL bf16 [ch][px] 128B rows,
// chunk swizzle ^(ch&7) (8KB each).
// ---------------------------------------------------------------------------
#define GF0    0
#define GF1    16384
#define GXH    32768
#define GXL    40960
#define G_SMEM 49152

__global__ void __launch_bounds__(128, 3)
gram_mma(const float* __restrict__ x) {
    extern __shared__ __align__(16) uint8_t smem[];
    const int t = threadIdx.x;
    const int w = t >> 5;
    const int lane = t & 31;

    float P1[4][2][4], P2[4][2][4];
#pragma unroll
    for (int mf = 0; mf < 4; mf++)
#pragma unroll
        for (int nf = 0; nf < 2; nf++)
#pragma unroll
            for (int e = 0; e < 4; e++) { P1[mf][nf][e] = 0.f; P2[mf][nf][e] = 0.f; }
    float csum[8];
#pragma unroll
    for (int q = 0; q < 8; q++) csum[q] = 0.f;

    const int rs = lane & 7;
    const uint32_t xh32 = smem_u32(smem + GXH), xl32 = smem_u32(smem + GXL);
    uint32_t aRowH[4], aRowL[4];
#pragma unroll
    for (int mf = 0; mf < 4; mf++) {
        const int row = (lane & 15) + mf * 16;
        aRowH[mf] = xh32 + row * 128;
        aRowL[mf] = xl32 + row * 128;
    }
    const int bRow = w * 16 + (lane & 7) + ((lane >> 4) << 3);
    const uint32_t bRowA = xh32 + bRow * 128;
    const int aCadd = (lane >> 4);
    const int bCadd = ((lane >> 3) & 1);
    // convert mapping: ch = 16w + 2q + (lane>>4), px = 4*(lane&15)
    const int cvH = lane >> 4, cvL = lane & 15;

    // prologue: stage tile0 -> F0
    {
        const int tau = blockIdx.x;
        const int n = tau >> 8, m0 = (tau & 255) << 6;
        const float* base = x + (size_t)(n * CCH) * HWSZ + m0;
#pragma unroll
        for (int i = 0; i < 8; i++) {
            const int chunk = t + 128 * i;
            const int ch = chunk >> 4, pc = chunk & 15;
            cpa16(smem + GF0 + ch * 256 + pc * 16, base + (size_t)ch * HWSZ + pc * 4);
        }
    }
    CP_COMMIT;

    int parity = 0;
    for (int tau = blockIdx.x; tau < NT2; tau += GBLK) {
        const int taun = tau + GBLK;
        uint8_t* nb = smem + (parity ? GF0 : GF1);
        if (taun < NT2) {
            const int n = taun >> 8, m0 = (taun & 255) << 6;
            const float* base = x + (size_t)(n * CCH) * HWSZ + m0;
#pragma unroll
            for (int i = 0; i < 8; i++) {
                const int chunk = t + 128 * i;
                const int ch = chunk >> 4, pc = chunk & 15;
                cpa16(nb + ch * 256 + pc * 16, base + (size_t)ch * HWSZ + pc * 4);
            }
        }
        CP_COMMIT;
        CP_WAIT1;
        __syncthreads();
        const float* fb = (const float*)(smem + (parity ? GF1 : GF0));

        // ---- convert staged fp32 -> XH/XL ----
#pragma unroll
        for (int q = 0; q < 8; q++) {
            const int ch = 16 * w + 2 * q + cvH;
            const float4 f4 = *(const float4*)(fb + ch * 64 + 4 * cvL);
            csum[q] += (f4.x + f4.y) + (f4.z + f4.w);
            const uint32_t h0 = cvt_bf2(f4.x, f4.y);
            const uint32_t h1 = cvt_bf2(f4.z, f4.w);
            const uint32_t l0 = cvt_bf2(f4.x - __uint_as_float(h0 << 16),
                                        f4.y - __uint_as_float(h0 & 0xFFFF0000u));
            const uint32_t l1 = cvt_bf2(f4.z - __uint_as_float(h1 << 16),
                                        f4.w - __uint_as_float(h1 & 0xFFFF0000u));
            const uint32_t so = ch * 128 + 16 * ((cvL >> 1) ^ (ch & 7)) + 8 * (cvL & 1);
            sts64(xh32 + so, h0, h1);
            sts64(xl32 + so, l0, l1);
        }
        __syncthreads();

        // ---- HMMA: 4 K-steps of 16 px ----
#pragma unroll
        for (int ks = 0; ks < 4; ks++) {
            const uint32_t offA = 16 * ((ks * 2 + aCadd) ^ rs);
            const uint32_t offB = 16 * ((ks * 2 + bCadd) ^ rs);
            uint32_t b[4];
            ldsm4(b, bRowA + offB);
            uint32_t ah[4][4], al[4][4];
#pragma unroll
            for (int mf = 0; mf < 4; mf++) ldsm4(ah[mf], aRowH[mf] + offA);
#pragma unroll
            for (int mf = 0; mf < 4; mf++) ldsm4(al[mf], aRowL[mf] + offA);
#pragma unroll
            for (int mf = 0; mf < 4; mf++) {
                mma16816(P1[mf][0], ah[mf], b[0], b[1]);
                mma16816(P1[mf][1], ah[mf], b[2], b[3]);
                mma16816(P2[mf][0], al[mf], b[0], b[1]);
                mma16816(P2[mf][1], al[mf], b[2], b[3]);
            }
        }
        __syncthreads();
        parity ^= 1;
    }

    // ---- epilogue ----
    float* p1 = g_p1 + (size_t)blockIdx.x * 4096;
    float* p2 = g_p2 + (size_t)blockIdx.x * 4096;
#pragma unroll
    for (int mf = 0; mf < 4; mf++)
#pragma unroll
        for (int nf = 0; nf < 2; nf++) {
            const int i = mf * 16 + (lane >> 2);
            const int j = w * 16 + nf * 8 + (lane & 3) * 2;
            *(float2*)(p1 + i * 64 + j)       = make_float2(P1[mf][nf][0], P1[mf][nf][1]);
            *(float2*)(p1 + (i + 8) * 64 + j) = make_float2(P1[mf][nf][2], P1[mf][nf][3]);
            *(float2*)(p2 + i * 64 + j)       = make_float2(P2[mf][nf][0], P2[mf][nf][1]);
            *(float2*)(p2 + (i + 8) * 64 + j) = make_float2(P2[mf][nf][2], P2[mf][nf][3]);
        }
    // channel sums: channel 16w+2q+cvH shared by the 16 lanes with same cvH
#pragma unroll
    for (int q = 0; q < 8; q++) {
        float s = csum[q];
#pragma unroll
        for (int off = 8; off > 0; off >>= 1)
            s += __shfl_down_sync(0xffffffffu, s, off, 16);
        if (cvL == 0) g_ps[blockIdx.x * 64 + 16 * w + 2 * q + cvH] = s;
    }
}

// ---------------------------------------------------------------------------
// Pass 1b: gram[i][j] = sum_g P1 + P2 + P2^T ; channel sums.
// ---------------------------------------------------------------------------
__global__ void reduce_kernel() {
    const int b = blockIdx.x, t = threadIdx.x;
    if (b < 256) {
        const int o = b * 16 + (t >> 3);
        const int i = o >> 6, j = o & 63;
        const int s = t & 7;
        const int g0 = s * 56;
        const int g1 = (g0 + 56 < GBLK) ? g0 + 56 : GBLK;
        const int ot = j * 64 + i;
        float acc = 0.f;
        for (int g = g0; g < g1; g++) {
            const size_t base = (size_t)g * 4096;
            acc += g_p1[base + o] + g_p2[base + o] + g_p2[base + ot];
        }
        acc += __shfl_down_sync(0xffffffffu, acc, 4);
        acc += __shfl_down_sync(0xffffffffu, acc, 2);
        acc += __shfl_down_sync(0xffffffffu, acc, 1);
        if (s == 0) g_gram[o] = acc;
    } else if (t < 64) {
        float s = 0.f;
        for (int g = 0; g < GBLK; g++) s += g_ps[g * 64 + t];
        g_S[t] = s;
    }
}

// ---------------------------------------------------------------------------
// Eigen kernel (unchanged).
// ---------------------------------------------------------------------------
__global__ void eigen_kernel(const float* __restrict__ weight,
                             const float* __restrict__ bias,
                             const float* __restrict__ vinit) {
    __shared__ float cov[64 * 65];
    __shared__ float v[64];
    __shared__ float wv[64];
    __shared__ float red[256];
    __shared__ float mu[64];
    __shared__ float Vs[KEIG * 64];
    __shared__ float lamArr[KEIG];
    __shared__ float invs[KEIG];
    __shared__ float scal;

    const int t = threadIdx.x;
    const float invM = 1.0f / 1048576.0f;

    if (t < 64) mu[t] = g_S[t] * invM;
    __syncthreads();
    for (int idx = t; idx < 4096; idx += 256) {
        const int ii = idx >> 6, jj = idx & 63;
        float c = g_gram[idx] * invM - mu[ii] * mu[jj];
        if (ii == jj) c += EPSV;
        cov[ii * 65 + jj] = c;
    }
    const int row = t & 63, part = t >> 6;
    __syncthreads();

    for (int k = 0; k < KEIG; k++) {
        if (t < 64) v[t] = vinit[k * 64 + t];
        __syncthreads();
        for (int it = 0; it < 10; it++) {
            float p = 0.0f;
#pragma unroll
            for (int q = 0; q < 16; q++)
                p += cov[row * 65 + part * 16 + q] * v[part * 16 + q];
            red[part * 64 + row] = p;
            __syncthreads();
            if (part == 0)
                v[row] = (red[row] + red[64 + row]) + (red[128 + row] + red[192 + row]);
            __syncthreads();
        }
        if (t < 64) red[t] = v[t] * v[t];
        __syncthreads();
        if (t < 32) {
            float s = red[t] + red[t + 32];
#pragma unroll
            for (int off = 16; off > 0; off >>= 1)
                s += __shfl_down_sync(0xffffffffu, s, off);
            if (t == 0) scal = 1.0f / sqrtf(s);
        }
        __syncthreads();
        if (t < 64) v[t] *= scal;
        __syncthreads();
        {
            float p = 0.0f;
#pragma unroll
            for (int q = 0; q < 16; q++)
                p += cov[row * 65 + part * 16 + q] * v[part * 16 + q];
            red[part * 64 + row] = p;
            __syncthreads();
            if (part == 0)
                wv[row] = (red[row] + red[64 + row]) + (red[128 + row] + red[192 + row]);
            __syncthreads();
        }
        if (t < 64) red[t] = v[t] * wv[t];
        __syncthreads();
        if (t < 32) {
            float s = red[t] + red[t + 32];
#pragma unroll
            for (int off = 16; off > 0; off >>= 1)
                s += __shfl_down_sync(0xffffffffu, s, off);
            if (t == 0) scal = s;
        }
        __syncthreads();
        const float lam = scal;
        if (t == 0) lamArr[k] = lam;
        if (t < 64) Vs[k * 64 + t] = v[t];
        __syncthreads();
        for (int idx = t; idx < 4096; idx += 256)
            cov[(idx >> 6) * 65 + (idx & 63)] -= lam * v[idx >> 6] * v[idx & 63];
        __syncthreads();
    }

    if (t < KEIG) invs[t] = 1.0f / sqrtf(lamArr[t] + EPSV);
    __syncthreads();
    for (int idx = t; idx < 4096; idx += 256) {
        const int c = idx >> 6, cp = idx & 63;
        float s = 0.0f;
#pragma unroll
        for (int k = 0; k < KEIG; k++)
            s += Vs[k * 64 + c] * invs[k] * Vs[k * 64 + cp];
        g_W[idx] = weight[c] * s;
    }
    __syncthreads();
    if (t < 64) {
        float s = bias[t];
        for (int cp = 0; cp < 64; cp++) s -= g_W[t * 64 + cp] * mu[cp];
        g_off[t] = s;
    }
}

// ---------------------------------------------------------------------------
// Pass 2: apply.  64ch x 64px tiles, staged.  3 CTAs/SM.
// W: [cout 64][Wh|Wl] 256B rows, chunk swizzle ^(cout&7) (16KB).
// F staging 2x16KB; XH/XL as in gram (8KB each).
// Warp w: m = all 64 cout, n-slice px [16w, 16w+16).
// ---------------------------------------------------------------------------
#define AW_OFF   0
#define AF0      16384
#define AF1      32768
#define AXH      49152
#define AXL      57344
#define ASOFF    65536
#define AP_SMEM  65792

__global__ void __launch_bounds__(128, 3)
apply_mma(const float* __restrict__ x, float* __restrict__ out) {
    extern __shared__ __align__(16) uint8_t smem[];
    const int t = threadIdx.x;
    const int w = t >> 5;
    const int lane = t & 31;

    // ---- build W = [Wh|Wl] swizzled rows, soff ----
    for (int idx = t; idx < 4096; idx += 128) {
        const int cout = idx >> 6, cin = idx & 63;
        const float wv = g_W[idx];
        const __nv_bfloat16 hb = __float2bfloat16(wv);
        const __nv_bfloat16 lb = __float2bfloat16(wv - __bfloat162float(hb));
        const uint32_t ck = (uint32_t)((cin >> 3) ^ (cout & 7));
        const uint32_t ib = (cin & 7) * 2;
        *(__nv_bfloat16*)(smem + AW_OFF + cout * 256 + ck * 16 + ib)        = hb;
        *(__nv_bfloat16*)(smem + AW_OFF + cout * 256 + (8 + ck) * 16 + ib)  = lb;
    }
    if (t < 64) *(float*)(smem + ASOFF + 4 * t) = g_off[t];

    const int rs = lane & 7;
    const uint32_t sw32 = smem_u32(smem + AW_OFF);
    const uint32_t xh32 = smem_u32(smem + AXH);
    const uint32_t xl32 = smem_u32(smem + AXL);
    uint32_t aRow[4];
#pragma unroll
    for (int mf = 0; mf < 4; mf++)
        aRow[mf] = sw32 + ((lane & 15) + mf * 16) * 256;
    const int aCadd = (lane >> 4);
    // B trans addressing: ch-row = (ks&3)*16 + bChOff; px chunk = 2w + (lane>>4)
    const uint32_t bChOff = (uint32_t)((lane & 7) + 8 * ((lane >> 3) & 1));
    const uint32_t bCk = (uint32_t)((2 * w + (lane >> 4)) ^ rs);
    const int cvH = lane >> 4, cvL = lane & 15;

    // prologue: stage tile0 -> F0
    {
        const int tau = blockIdx.x;
        const int n = tau >> 8, m0 = (tau & 255) << 6;
        const float* base = x + (size_t)(n * CCH) * HWSZ + m0;
#pragma unroll
        for (int i = 0; i < 8; i++) {
            const int chunk = t + 128 * i;
            const int ch = chunk >> 4, pc = chunk & 15;
            cpa16(smem + AF0 + ch * 256 + pc * 16, base + (size_t)ch * HWSZ + pc * 4);
        }
    }
    CP_COMMIT;
    __syncthreads();   // W table ready

    const float* soff = (const float*)(smem + ASOFF);
    float offv[4][2];
#pragma unroll
    for (int mf = 0; mf < 4; mf++) {
        offv[mf][0] = soff[mf * 16 + (lane >> 2)];
        offv[mf][1] = soff[mf * 16 + (lane >> 2) + 8];
    }

    int parity = 0;
    for (int tau = blockIdx.x; tau < NT2; tau += GBLK) {
        const int taun = tau + GBLK;
        uint8_t* nb = smem + (parity ? AF0 : AF1);
        if (taun < NT2) {
            const int n = taun >> 8, m0 = (taun & 255) << 6;
            const float* base = x + (size_t)(n * CCH) * HWSZ + m0;
#pragma unroll
            for (int i = 0; i < 8; i++) {
                const int chunk = t + 128 * i;
                const int ch = chunk >> 4, pc = chunk & 15;
                cpa16(nb + ch * 256 + pc * 16, base + (size_t)ch * HWSZ + pc * 4);
            }
        }
        CP_COMMIT;
        CP_WAIT1;
        __syncthreads();
        const float* fb = (const float*)(smem + (parity ? AF1 : AF0));

        // ---- convert staged fp32 -> XH/XL ----
#pragma unroll
        for (int q = 0; q < 8; q++) {
            const int ch = 16 * w + 2 * q + cvH;
            const float4 f4 = *(const float4*)(fb + ch * 64 + 4 * cvL);
            const uint32_t h0 = cvt_bf2(f4.x, f4.y);
            const uint32_t h1 = cvt_bf2(f4.z, f4.w);
            const uint32_t l0 = cvt_bf2(f4.x - __uint_as_float(h0 << 16),
                                        f4.y - __uint_as_float(h0 & 0xFFFF0000u));
            const uint32_t l1 = cvt_bf2(f4.z - __uint_as_float(h1 << 16),
                                        f4.w - __uint_as_float(h1 & 0xFFFF0000u));
            const uint32_t so = ch * 128 + 16 * ((cvL >> 1) ^ (ch & 7)) + 8 * (cvL & 1);
            sts64(xh32 + so, h0, h1);
            sts64(xl32 + so, l0, l1);
        }
        __syncthreads();

        // ---- acc init with offsets ----
        float acc[4][2][4];
#pragma unroll
        for (int mf = 0; mf < 4; mf++)
#pragma unroll
            for (int nf = 0; nf < 2; nf++) {
                acc[mf][nf][0] = offv[mf][0]; acc[mf][nf][1] = offv[mf][0];
                acc[mf][nf][2] = offv[mf][1]; acc[mf][nf][3] = offv[mf][1];
            }

        // ---- HMMA: 12 K-steps (Wh.xh x4, Wl.xh x4, Wh.xl x4) ----
#pragma unroll
        for (int ks = 0; ks < 12; ks++) {
            const uint32_t xb = (ks < 8) ? xh32 : xl32;
            const int seg = (ks >= 4 && ks < 8) ? 8 : 0;       // Wl segment
            const uint32_t offA = 16 * ((seg + (ks & 3) * 2 + aCadd) ^ rs);
            const uint32_t chRow = ((uint32_t)(ks & 3) * 16 + bChOff) * 128;
            uint32_t a[4][4];
#pragma unroll
            for (int mf = 0; mf < 4; mf++) ldsm4(a[mf], aRow[mf] + offA);
            uint32_t b[4];
            ldsm4t(b, xb + chRow + 16 * bCk);
#pragma unroll
            for (int mf = 0; mf < 4; mf++) {
                mma16816(acc[mf][0], a[mf], b[0], b[1]);
                mma16816(acc[mf][1], a[mf], b[2], b[3]);
            }
        }

        // ---- epilogue: out[cout][px], warp px slice 16w ----
        const int n = tau >> 8, m0 = (tau & 255) << 6;
        float* ob = out + (size_t)(n * CCH) * HWSZ + m0 + w * 16 + (lane & 3) * 2;
#pragma unroll
        for (int mf = 0; mf < 4; mf++) {
            const int cout = mf * 16 + (lane >> 2);
#pragma unroll
            for (int nf = 0; nf < 2; nf++) {
                float* p = ob + nf * 8;
                *(float2*)(p + (size_t)cout * HWSZ)       = make_float2(acc[mf][nf][0], acc[mf][nf][1]);
                *(float2*)(p + (size_t)(cout + 8) * HWSZ) = make_float2(acc[mf][nf][2], acc[mf][nf][3]);
            }
        }
        __syncthreads();
        parity ^= 1;
    }
}

// ---------------------------------------------------------------------------
extern "C" void kernel_launch(void* const* d_in, const int* in_sizes, int n_in,
                              void* d_out, int out_size) {
    const float* x      = (const float*)d_in[0];
    const float* weight = (const float*)d_in[1];
    const float* bias   = (const float*)d_in[2];
    const float* vinit  = (const float*)d_in[3];
    float* out = (float*)d_out;

    cudaFuncSetAttribute(gram_mma,
                         cudaFuncAttributeMaxDynamicSharedMemorySize, G_SMEM);
    cudaFuncSetAttribute(apply_mma,
                         cudaFuncAttributeMaxDynamicSharedMemorySize, AP_SMEM);

    gram_mma<<<GBLK, 128, G_SMEM>>>(x);
    reduce_kernel<<<257, 128>>>();
    eigen_kernel<<<1, 256>>>(weight, bias, vinit);
    apply_mma<<<GBLK, 128, AP_SMEM>>>(x, out);
}

// round 12
// speedup vs baseline: 1.0510x; 1.0510x over previous
#include <cuda_runtime.h>
#include <cuda_bf16.h>
#include <cstdint>

// ---------------------------------------------------------------------------
// PCA-whitening norm. x: [64,64,128,128] fp32.  HMMA, 64-px tiles.
//   1. gram_mma  : staged fp32 -> bf16 h/l -> P1=xh@xh^T, P2=xl@xh^T
//                  warp tile 32x32, 6 ldsm / K-step
//   2. reduce_kernel : gram = sum(P1 + P2 + P2^T), channel sums
//   3. eigen_kernel  : -> g_W, g_off
//   4. apply_mma : out = W@x + off, K=192 bf16-split HMMA,
//                  W A-fragments hoisted to registers (16 ldsm total),
//                  warp tile 32cout x 32px, direct-LDG convert.
// ---------------------------------------------------------------------------

#define CCH    64
#define HWSZ   16384
#define NT2    16384         // 64-px tiles
#define GBLK   444
#define KEIG   32
#define EPSV   1e-5f

__device__ float g_p1[GBLK * 4096];
__device__ float g_p2[GBLK * 4096];
__device__ float g_ps[GBLK * 64];
__device__ float g_gram[4096];
__device__ float g_S[64];
__device__ float g_W[4096];
__device__ float g_off[64];

// ---------------- helpers ----------------
__device__ __forceinline__ uint32_t smem_u32(const void* p) {
    return (uint32_t)__cvta_generic_to_shared(p);
}
__device__ __forceinline__ uint32_t cvt_bf2(float a, float b) {
    uint32_t d;
    asm("cvt.rn.bf16x2.f32 %0, %1, %2;" : "=r"(d) : "f"(b), "f"(a));
    return d;
}
__device__ __forceinline__ void ldsm4(uint32_t* r, uint32_t addr) {
    asm volatile("ldmatrix.sync.aligned.m8n8.x4.shared.b16 {%0,%1,%2,%3}, [%4];"
                 : "=r"(r[0]), "=r"(r[1]), "=r"(r[2]), "=r"(r[3]) : "r"(addr));
}
__device__ __forceinline__ void ldsm4t(uint32_t* r, uint32_t addr) {
    asm volatile("ldmatrix.sync.aligned.m8n8.x4.trans.shared.b16 {%0,%1,%2,%3}, [%4];"
                 : "=r"(r[0]), "=r"(r[1]), "=r"(r[2]), "=r"(r[3]) : "r"(addr));
}
__device__ __forceinline__ void mma16816(float* d, const uint32_t* a,
                                         uint32_t b0, uint32_t b1) {
    asm volatile("mma.sync.aligned.m16n8k16.row.col.f32.bf16.bf16.f32 "
                 "{%0,%1,%2,%3}, {%4,%5,%6,%7}, {%8,%9}, {%0,%1,%2,%3};"
                 : "+f"(d[0]), "+f"(d[1]), "+f"(d[2]), "+f"(d[3])
                 : "r"(a[0]), "r"(a[1]), "r"(a[2]), "r"(a[3]), "r"(b0), "r"(b1));
}
__device__ __forceinline__ void sts64(uint32_t addr, uint32_t r0, uint32_t r1) {
    asm volatile("st.shared.v2.b32 [%0], {%1, %2};" :: "r"(addr), "r"(r0), "r"(r1));
}
__device__ __forceinline__ void cpa16(void* s, const void* g) {
    uint32_t sa = (uint32_t)__cvta_generic_to_shared(s);
    asm volatile("cp.async.cg.shared.global [%0], [%1], 16;" :: "r"(sa), "l"(g));
}
#define CP_COMMIT asm volatile("cp.async.commit_group;")
#define CP_WAIT1  asm volatile("cp.async.wait_group 1;")

// ---------------------------------------------------------------------------
// Pass 1: gram.  64ch x 64px tiles, staged, 3 CTAs/SM, warp tile 32x32.
// ---------------------------------------------------------------------------
#define GF0    0
#define GF1    16384
#define GXH    32768
#define GXL    40960
#define G_SMEM 49152

__global__ void __launch_bounds__(128, 3)
gram_mma(const float* __restrict__ x) {
    extern __shared__ __align__(16) uint8_t smem[];
    const int t = threadIdx.x;
    const int w = t >> 5;
    const int lane = t & 31;
    const int mH = 32 * (w & 1);      // m (row-channel) half
    const int nH = 32 * (w >> 1);     // n (col-channel) half

    float P1[2][4][4], P2[2][4][4];
#pragma unroll
    for (int mf = 0; mf < 2; mf++)
#pragma unroll
        for (int nf = 0; nf < 4; nf++)
#pragma unroll
            for (int e = 0; e < 4; e++) { P1[mf][nf][e] = 0.f; P2[mf][nf][e] = 0.f; }
    float csum[8];
#pragma unroll
    for (int q = 0; q < 8; q++) csum[q] = 0.f;

    const int rs = lane & 7;
    const uint32_t xh32 = smem_u32(smem + GXH), xl32 = smem_u32(smem + GXL);
    uint32_t aRowH[2], aRowL[2];
#pragma unroll
    for (int mf = 0; mf < 2; mf++) {
        const int row = mH + mf * 16 + (lane & 15);
        aRowH[mf] = xh32 + row * 128;
        aRowL[mf] = xl32 + row * 128;
    }
    uint32_t bRowA[2];
#pragma unroll
    for (int j = 0; j < 2; j++) {
        const int row = nH + j * 16 + (lane & 7) + ((lane >> 4) << 3);
        bRowA[j] = xh32 + row * 128;
    }
    const int aCadd = (lane >> 4);
    const int bCadd = ((lane >> 3) & 1);
    const int cvH = lane >> 4, cvL = lane & 15;

    // prologue: stage tile0 -> F0
    {
        const int tau = blockIdx.x;
        const int n = tau >> 8, m0 = (tau & 255) << 6;
        const float* base = x + (size_t)(n * CCH) * HWSZ + m0;
#pragma unroll
        for (int i = 0; i < 8; i++) {
            const int chunk = t + 128 * i;
            const int ch = chunk >> 4, pc = chunk & 15;
            cpa16(smem + GF0 + ch * 256 + pc * 16, base + (size_t)ch * HWSZ + pc * 4);
        }
    }
    CP_COMMIT;

    int parity = 0;
    for (int tau = blockIdx.x; tau < NT2; tau += GBLK) {
        const int taun = tau + GBLK;
        uint8_t* nb = smem + (parity ? GF0 : GF1);
        if (taun < NT2) {
            const int n = taun >> 8, m0 = (taun & 255) << 6;
            const float* base = x + (size_t)(n * CCH) * HWSZ + m0;
#pragma unroll
            for (int i = 0; i < 8; i++) {
                const int chunk = t + 128 * i;
                const int ch = chunk >> 4, pc = chunk & 15;
                cpa16(nb + ch * 256 + pc * 16, base + (size_t)ch * HWSZ + pc * 4);
            }
        }
        CP_COMMIT;
        CP_WAIT1;
        __syncthreads();
        const float* fb = (const float*)(smem + (parity ? GF1 : GF0));

        // ---- convert staged fp32 -> XH/XL ----
#pragma unroll
        for (int q = 0; q < 8; q++) {
            const int ch = 16 * w + 2 * q + cvH;
            const float4 f4 = *(const float4*)(fb + ch * 64 + 4 * cvL);
            csum[q] += (f4.x + f4.y) + (f4.z + f4.w);
            const uint32_t h0 = cvt_bf2(f4.x, f4.y);
            const uint32_t h1 = cvt_bf2(f4.z, f4.w);
            const uint32_t l0 = cvt_bf2(f4.x - __uint_as_float(h0 << 16),
                                        f4.y - __uint_as_float(h0 & 0xFFFF0000u));
            const uint32_t l1 = cvt_bf2(f4.z - __uint_as_float(h1 << 16),
                                        f4.w - __uint_as_float(h1 & 0xFFFF0000u));
            const uint32_t so = ch * 128 + 16 * ((cvL >> 1) ^ (ch & 7)) + 8 * (cvL & 1);
            sts64(xh32 + so, h0, h1);
            sts64(xl32 + so, l0, l1);
        }
        __syncthreads();

        // ---- HMMA: 4 K-steps of 16 px; 6 ldsm + 16 MMA each ----
#pragma unroll
        for (int ks = 0; ks < 4; ks++) {
            const uint32_t offA = 16 * ((ks * 2 + aCadd) ^ rs);
            const uint32_t offB = 16 * ((ks * 2 + bCadd) ^ rs);
            uint32_t b[2][4];
            ldsm4(b[0], bRowA[0] + offB);
            ldsm4(b[1], bRowA[1] + offB);
            uint32_t ah[2][4], al[2][4];
#pragma unroll
            for (int mf = 0; mf < 2; mf++) ldsm4(ah[mf], aRowH[mf] + offA);
#pragma unroll
            for (int mf = 0; mf < 2; mf++) ldsm4(al[mf], aRowL[mf] + offA);
#pragma unroll
            for (int mf = 0; mf < 2; mf++)
#pragma unroll
                for (int j = 0; j < 2; j++) {
                    mma16816(P1[mf][2 * j],     ah[mf], b[j][0], b[j][1]);
                    mma16816(P1[mf][2 * j + 1], ah[mf], b[j][2], b[j][3]);
                    mma16816(P2[mf][2 * j],     al[mf], b[j][0], b[j][1]);
                    mma16816(P2[mf][2 * j + 1], al[mf], b[j][2], b[j][3]);
                }
        }
        __syncthreads();
        parity ^= 1;
    }

    // ---- epilogue ----
    float* p1 = g_p1 + (size_t)blockIdx.x * 4096;
    float* p2 = g_p2 + (size_t)blockIdx.x * 4096;
#pragma unroll
    for (int mf = 0; mf < 2; mf++)
#pragma unroll
        for (int nf = 0; nf < 4; nf++) {
            const int i = mH + mf * 16 + (lane >> 2);
            const int j = nH + nf * 8 + (lane & 3) * 2;
            *(float2*)(p1 + i * 64 + j)       = make_float2(P1[mf][nf][0], P1[mf][nf][1]);
            *(float2*)(p1 + (i + 8) * 64 + j) = make_float2(P1[mf][nf][2], P1[mf][nf][3]);
            *(float2*)(p2 + i * 64 + j)       = make_float2(P2[mf][nf][0], P2[mf][nf][1]);
            *(float2*)(p2 + (i + 8) * 64 + j) = make_float2(P2[mf][nf][2], P2[mf][nf][3]);
        }
#pragma unroll
    for (int q = 0; q < 8; q++) {
        float s = csum[q];
#pragma unroll
        for (int off = 8; off > 0; off >>= 1)
            s += __shfl_down_sync(0xffffffffu, s, off, 16);
        if (cvL == 0) g_ps[blockIdx.x * 64 + 16 * w + 2 * q + cvH] = s;
    }
}

// ---------------------------------------------------------------------------
__global__ void reduce_kernel() {
    const int b = blockIdx.x, t = threadIdx.x;
    if (b < 256) {
        const int o = b * 16 + (t >> 3);
        const int i = o >> 6, j = o & 63;
        const int s = t & 7;
        const int g0 = s * 56;
        const int g1 = (g0 + 56 < GBLK) ? g0 + 56 : GBLK;
        const int ot = j * 64 + i;
        float acc = 0.f;
        for (int g = g0; g < g1; g++) {
            const size_t base = (size_t)g * 4096;
            acc += g_p1[base + o] + g_p2[base + o] + g_p2[base + ot];
        }
        acc += __shfl_down_sync(0xffffffffu, acc, 4);
        acc += __shfl_down_sync(0xffffffffu, acc, 2);
        acc += __shfl_down_sync(0xffffffffu, acc, 1);
        if (s == 0) g_gram[o] = acc;
    } else if (t < 64) {
        float s = 0.f;
        for (int g = 0; g < GBLK; g++) s += g_ps[g * 64 + t];
        g_S[t] = s;
    }
}

// ---------------------------------------------------------------------------
// Eigen kernel (unchanged).
// ---------------------------------------------------------------------------
__global__ void eigen_kernel(const float* __restrict__ weight,
                             const float* __restrict__ bias,
                             const float* __restrict__ vinit) {
    __shared__ float cov[64 * 65];
    __shared__ float v[64];
    __shared__ float wv[64];
    __shared__ float red[256];
    __shared__ float mu[64];
    __shared__ float Vs[KEIG * 64];
    __shared__ float lamArr[KEIG];
    __shared__ float invs[KEIG];
    __shared__ float scal;

    const int t = threadIdx.x;
    const float invM = 1.0f / 1048576.0f;

    if (t < 64) mu[t] = g_S[t] * invM;
    __syncthreads();
    for (int idx = t; idx < 4096; idx += 256) {
        const int ii = idx >> 6, jj = idx & 63;
        float c = g_gram[idx] * invM - mu[ii] * mu[jj];
        if (ii == jj) c += EPSV;
        cov[ii * 65 + jj] = c;
    }
    const int row = t & 63, part = t >> 6;
    __syncthreads();

    for (int k = 0; k < KEIG; k++) {
        if (t < 64) v[t] = vinit[k * 64 + t];
        __syncthreads();
        for (int it = 0; it < 10; it++) {
            float p = 0.0f;
#pragma unroll
            for (int q = 0; q < 16; q++)
                p += cov[row * 65 + part * 16 + q] * v[part * 16 + q];
            red[part * 64 + row] = p;
            __syncthreads();
            if (part == 0)
                v[row] = (red[row] + red[64 + row]) + (red[128 + row] + red[192 + row]);
            __syncthreads();
        }
        if (t < 64) red[t] = v[t] * v[t];
        __syncthreads();
        if (t < 32) {
            float s = red[t] + red[t + 32];
#pragma unroll
            for (int off = 16; off > 0; off >>= 1)
                s += __shfl_down_sync(0xffffffffu, s, off);
            if (t == 0) scal = 1.0f / sqrtf(s);
        }
        __syncthreads();
        if (t < 64) v[t] *= scal;
        __syncthreads();
        {
            float p = 0.0f;
#pragma unroll
            for (int q = 0; q < 16; q++)
                p += cov[row * 65 + part * 16 + q] * v[part * 16 + q];
            red[part * 64 + row] = p;
            __syncthreads();
            if (part == 0)
                wv[row] = (red[row] + red[64 + row]) + (red[128 + row] + red[192 + row]);
            __syncthreads();
        }
        if (t < 64) red[t] = v[t] * wv[t];
        __syncthreads();
        if (t < 32) {
            float s = red[t] + red[t + 32];
#pragma unroll
            for (int off = 16; off > 0; off >>= 1)
                s += __shfl_down_sync(0xffffffffu, s, off);
            if (t == 0) scal = s;
        }
        __syncthreads();
        const float lam = scal;
        if (t == 0) lamArr[k] = lam;
        if (t < 64) Vs[k * 64 + t] = v[t];
        __syncthreads();
        for (int idx = t; idx < 4096; idx += 256)
            cov[(idx >> 6) * 65 + (idx & 63)] -= lam * v[idx >> 6] * v[idx & 63];
        __syncthreads();
    }

    if (t < KEIG) invs[t] = 1.0f / sqrtf(lamArr[t] + EPSV);
    __syncthreads();
    for (int idx = t; idx < 4096; idx += 256) {
        const int c = idx >> 6, cp = idx & 63;
        float s = 0.0f;
#pragma unroll
        for (int k = 0; k < KEIG; k++)
            s += Vs[k * 64 + c] * invs[k] * Vs[k * 64 + cp];
        g_W[idx] = weight[c] * s;
    }
    __syncthreads();
    if (t < 64) {
        float s = bias[t];
        for (int cp = 0; cp < 64; cp++) s -= g_W[t * 64 + cp] * mu[cp];
        g_off[t] = s;
    }
}

// ---------------------------------------------------------------------------
// Pass 2: apply.  64ch x 64px tiles, warp tile 32cout x 32px.
// W: [cout 64][Wh|Wl] 256B rows, chunk swizzle ^(cout&7) (16KB);
// A-fragments hoisted to registers (16 ldsm, once).
// XH/XL bf16 [ch][px] 128B rows, swizzle ^(ch&7); direct-LDG convert.
// ---------------------------------------------------------------------------
#define AW_OFF   0
#define AXH      16384
#define AXL      24576
#define ASOFF    32768
#define AP_SMEM  33024

__global__ void __launch_bounds__(128, 3)
apply_mma(const float* __restrict__ x, float* __restrict__ out) {
    extern __shared__ __align__(16) uint8_t smem[];
    const int t = threadIdx.x;
    const int w = t >> 5;
    const int lane = t & 31;
    const int mH = 32 * (w & 1);      // cout half
    const int pH = 32 * (w >> 1);     // px half
    const int cbase = pH >> 3;        // px chunk base

    // ---- build W = [Wh|Wl] swizzled rows, soff ----
    for (int idx = t; idx < 4096; idx += 128) {
        const int cout = idx >> 6, cin = idx & 63;
        const float wv = g_W[idx];
        const __nv_bfloat16 hb = __float2bfloat16(wv);
        const __nv_bfloat16 lb = __float2bfloat16(wv - __bfloat162float(hb));
        const uint32_t ck = (uint32_t)((cin >> 3) ^ (cout & 7));
        const uint32_t ib = (cin & 7) * 2;
        *(__nv_bfloat16*)(smem + AW_OFF + cout * 256 + ck * 16 + ib)        = hb;
        *(__nv_bfloat16*)(smem + AW_OFF + cout * 256 + (8 + ck) * 16 + ib)  = lb;
    }
    if (t < 64) *(float*)(smem + ASOFF + 4 * t) = g_off[t];
    __syncthreads();

    const int rs = lane & 7;
    const int aCadd = (lane >> 4);
    const uint32_t sw32 = smem_u32(smem + AW_OFF);
    const uint32_t xh32 = smem_u32(smem + AXH);
    const uint32_t xl32 = smem_u32(smem + AXL);

    // ---- hoist W A-fragments: aw[mf][0..3]=Wh ks0-3, [4..7]=Wl ks0-3 ----
    uint32_t aw[2][8][4];
#pragma unroll
    for (int mf = 0; mf < 2; mf++) {
        const uint32_t aRow = sw32 + (mH + mf * 16 + (lane & 15)) * 256;
#pragma unroll
        for (int s = 0; s < 2; s++)
#pragma unroll
            for (int kk = 0; kk < 4; kk++)
                ldsm4(aw[mf][s * 4 + kk],
                      aRow + 16 * ((s * 8 + kk * 2 + aCadd) ^ rs));
    }

    const uint32_t bChOff = (uint32_t)((lane & 7) + 8 * ((lane >> 3) & 1));
    const float* soff = (const float*)(smem + ASOFF);
    float offv[2][2];
#pragma unroll
    for (int mf = 0; mf < 2; mf++) {
        offv[mf][0] = soff[mH + mf * 16 + (lane >> 2)];
        offv[mf][1] = soff[mH + mf * 16 + (lane >> 2) + 8];
    }
    const int chb = 8 * (t >> 4);
    const int pc = t & 15;

    for (int tau = blockIdx.x; tau < NT2; tau += GBLK) {
        const int n = tau >> 8, m0 = (tau & 255) << 6;

        // ---- convert: direct LDG.128, thread = (8-ch group, 4-px group) ----
        {
            const float* bx = x + (size_t)(n * CCH) * HWSZ + m0 + 4 * pc;
#pragma unroll
            for (int q = 0; q < 8; q++) {
                const int ch = chb + q;
                const float4 f4 = *(const float4*)(bx + (size_t)ch * HWSZ);
                const uint32_t h0 = cvt_bf2(f4.x, f4.y);
                const uint32_t h1 = cvt_bf2(f4.z, f4.w);
                const uint32_t l0 = cvt_bf2(f4.x - __uint_as_float(h0 << 16),
                                            f4.y - __uint_as_float(h0 & 0xFFFF0000u));
                const uint32_t l1 = cvt_bf2(f4.z - __uint_as_float(h1 << 16),
                                            f4.w - __uint_as_float(h1 & 0xFFFF0000u));
                const uint32_t so = ch * 128 + 16 * ((pc >> 1) ^ (ch & 7)) + 8 * (pc & 1);
                sts64(xh32 + so, h0, h1);
                sts64(xl32 + so, l0, l1);
            }
        }
        __syncthreads();

        // ---- acc init with offsets ----
        float acc[2][4][4];
#pragma unroll
        for (int mf = 0; mf < 2; mf++)
#pragma unroll
            for (int nf = 0; nf < 4; nf++) {
                acc[mf][nf][0] = offv[mf][0]; acc[mf][nf][1] = offv[mf][0];
                acc[mf][nf][2] = offv[mf][1]; acc[mf][nf][3] = offv[mf][1];
            }

        // ---- HMMA: 12 K-steps, 2 B-ldsm + 8 MMA each; A from registers ----
#pragma unroll
        for (int ks = 0; ks < 12; ks++) {
            const uint32_t xb = (ks < 8) ? xh32 : xl32;
            const int ai = (ks < 8) ? ks : ks - 8;
            const uint32_t chRow = ((uint32_t)(ks & 3) * 16 + bChOff) * 128;
            uint32_t b[2][4];
#pragma unroll
            for (int j = 0; j < 2; j++)
                ldsm4t(b[j], xb + chRow + 16 * ((cbase + 2 * j + (lane >> 4)) ^ rs));
#pragma unroll
            for (int mf = 0; mf < 2; mf++)
#pragma unroll
                for (int j = 0; j < 2; j++) {
                    mma16816(acc[mf][2 * j],     aw[mf][ai], b[j][0], b[j][1]);
                    mma16816(acc[mf][2 * j + 1], aw[mf][ai], b[j][2], b[j][3]);
                }
        }

        // ---- epilogue: out[cout][px] ----
        float* ob = out + (size_t)(n * CCH) * HWSZ + m0 + pH + (lane & 3) * 2;
#pragma unroll
        for (int mf = 0; mf < 2; mf++) {
            const int cout = mH + mf * 16 + (lane >> 2);
#pragma unroll
            for (int nf = 0; nf < 4; nf++) {
                float* p = ob + nf * 8;
                *(float2*)(p + (size_t)cout * HWSZ)       = make_float2(acc[mf][nf][0], acc[mf][nf][1]);
                *(float2*)(p + (size_t)(cout + 8) * HWSZ) = make_float2(acc[mf][nf][2], acc[mf][nf][3]);
            }
        }
        __syncthreads();
    }
}

// ---------------------------------------------------------------------------
extern "C" void kernel_launch(void* const* d_in, const int* in_sizes, int n_in,
                              void* d_out, int out_size) {
    const float* x      = (const float*)d_in[0];
    const float* weight = (const float*)d_in[1];
    const float* bias   = (const float*)d_in[2];
    const float* vinit  = (const float*)d_in[3];
    float* out = (float*)d_out;

    cudaFuncSetAttribute(gram_mma,
                         cudaFuncAttributeMaxDynamicSharedMemorySize, G_SMEM);
    cudaFuncSetAttribute(apply_mma,
                         cudaFuncAttributeMaxDynamicSharedMemorySize, AP_SMEM);

    gram_mma<<<GBLK, 128, G_SMEM>>>(x);
    reduce_kernel<<<257, 128>>>();
    eigen_kernel<<<1, 256>>>(weight, bias, vinit);
    apply_mma<<<GBLK, 128, AP_SMEM>>>(x, out);
}